// round 12
// baseline (speedup 1.0000x reference)
#include <cuda_runtime.h>
#include <cuda_bf16.h>
#include <cstdint>

// Round 12 = round 11 + (a) hist: single packed 64-bit atomic carrying
// {count, fixed-point deg}, rank still free from the return value;
// (b) scatter + hist: 4 edges/thread with int4 loads for MLP.

#define N_NODES 100000
#define N_EDGES 1000000
#define D 64
#define ALPHA 10.0f
#define NBLK_SCAN 391    // ceil(100000/256)
#define GTILES 1563      // ceil(100000/64)
#define AGG_FLAG 0x40000000
#define EBLKS 977        // ceil(1000000/4/256)
#define DEG_BIAS (1ll << 22)
#define DEG_SCALE 1048576.0f   // 2^20

// ---------------- scratch (device globals; zero-init at module load) ------
__device__ unsigned long long g_pk[N_NODES];  // {cnt<<40 | biased fixed deg}; self-cleaned
__device__ int   g_row[N_NODES + 1];
__device__ int   g_agg[NBLK_SCAN];
__device__ int   g_rank[N_EDGES];
__device__ int   g_perm[N_EDGES];
__device__ float g_norm[N_NODES];
__device__ float g_S1n[N_NODES * D];
__device__ float g_S2n[N_NODES * D];

// ---------------- histogram: ONE packed atomic per edge ----------------
__global__ void hist_kernel(const int* __restrict__ dst,
                            const int* __restrict__ e_feat,
                            const float* __restrict__ edge_weight) {
    int base = 4 * (blockIdx.x * blockDim.x + threadIdx.x);
    if (base >= N_EDGES) return;
    int4 d4 = *(const int4*)(dst + base);
    int4 t4 = *(const int4*)(e_feat + base);
    int ds[4] = {d4.x, d4.y, d4.z, d4.w};
    int ts[4] = {t4.x, t4.y, t4.z, t4.w};
#pragma unroll
    for (int i = 0; i < 4; i++) {
        float x = edge_weight[ts[i] - 1] * ALPHA;
        float w = x > 0.f ? x : 0.01f * x;   // leaky_relu
        long long fx = (long long)lrintf(w * DEG_SCALE) + DEG_BIAS;  // >= 0
        unsigned long long pack = (1ull << 40) | (unsigned long long)fx;
        unsigned long long old = atomicAdd(&g_pk[ds[i]], pack);
        g_rank[base + i] = (int)(old >> 40);
    }
}

// ---------------- fused scan (lookback) + norm + self-clean ----------------
__global__ __launch_bounds__(256) void scan_fused_kernel() {
    int tid = threadIdx.x, b = blockIdx.x;
    int i = b * 256 + tid;
    int v = 0;
    float deg = 0.f;
    if (i < N_NODES) {
        unsigned long long pk = g_pk[i];
        v = (int)(pk >> 40);
        long long fx = (long long)(pk & ((1ull << 40) - 1)) - (long long)v * DEG_BIAS;
        deg = (float)fx * (1.0f / DEG_SCALE);
    }

    __shared__ int rd[256];
    rd[tid] = v;
    __syncthreads();
    for (int o = 128; o > 0; o >>= 1) {
        if (tid < o) rd[tid] += rd[tid + o];
        __syncthreads();
    }
    if (tid == 0) atomicExch(&g_agg[b], rd[0] | AGG_FLAG);

    int acc = 0;
    for (int j = tid; j < b; j += 256) {
        int a;
        do { a = ((volatile int*)g_agg)[j]; } while (!(a & AGG_FLAG));
        acc += a & (AGG_FLAG - 1);
    }
    __syncthreads();
    rd[tid] = acc;
    __syncthreads();
    for (int o = 128; o > 0; o >>= 1) {
        if (tid < o) rd[tid] += rd[tid + o];
        __syncthreads();
    }
    int block_off = rd[0];

    unsigned lane = tid & 31, wid = tid >> 5;
    int x = v;
    for (int o = 1; o < 32; o <<= 1) {
        int y = __shfl_up_sync(0xffffffffu, x, o);
        if (lane >= o) x += y;
    }
    __shared__ int ws[8];
    if (lane == 31) ws[wid] = x;
    __syncthreads();
    if (wid == 0) {
        int s = (lane < 8) ? ws[lane] : 0;
        for (int o = 1; o < 8; o <<= 1) {
            int y = __shfl_up_sync(0xffffffffu, s, o);
            if (lane >= o) s += y;
        }
        if (lane < 8) ws[lane] = s;
    }
    __syncthreads();
    int excl = x - v + (wid ? ws[wid - 1] : 0) + block_off;
    if (i < N_NODES) {
        g_row[i] = excl;
        g_norm[i] = rsqrtf(fmaxf(deg, 1.0f));
        g_pk[i] = 0ull;        // self-clean
        if (i == N_NODES - 1) g_row[N_NODES] = excl + v;
    }
}

// ---------------- scatter: atomic-free, 4 edges/thread ----------------
__global__ void scatter_kernel(const int* __restrict__ src,
                               const int* __restrict__ dst) {
    int gi = blockIdx.x * blockDim.x + threadIdx.x;
    if (gi < NBLK_SCAN) g_agg[gi] = 0;    // reset lookback flags for next replay
    int base = 4 * gi;
    if (base >= N_EDGES) return;
    int4 d4 = *(const int4*)(dst + base);
    int4 s4 = *(const int4*)(src + base);
    int4 r4 = *(const int4*)(g_rank + base);
    int p0 = g_row[d4.x] + r4.x;
    int p1 = g_row[d4.y] + r4.y;
    int p2 = g_row[d4.z] + r4.z;
    int p3 = g_row[d4.w] + r4.w;
    g_perm[p0] = s4.x;
    g_perm[p1] = s4.y;
    g_perm[p2] = s4.z;
    g_perm[p3] = s4.w;
}

// ---------------- gather pass 1: S1n = norm * A*(norm*feats) ----------------
__global__ __launch_bounds__(256) void gather1_kernel(const float* __restrict__ feats) {
    int t = blockIdx.x * 256 + threadIdx.x;
    int n = t >> 4, c = t & 15;
    int e = g_row[n];
    int eend = g_row[n + 1];
    float4 acc = make_float4(0.f, 0.f, 0.f, 0.f);
    const float4* F = (const float4*)feats;
    for (; e + 3 < eend; e += 4) {
        int s0 = g_perm[e], s1 = g_perm[e + 1];
        int s2 = g_perm[e + 2], s3 = g_perm[e + 3];
        float n0 = g_norm[s0], n1 = g_norm[s1];
        float n2 = g_norm[s2], n3 = g_norm[s3];
        float4 a = F[s0 * 16 + c];
        float4 b = F[s1 * 16 + c];
        float4 cc = F[s2 * 16 + c];
        float4 dd = F[s3 * 16 + c];
        acc.x = fmaf(n0, a.x, fmaf(n1, b.x, fmaf(n2, cc.x, fmaf(n3, dd.x, acc.x))));
        acc.y = fmaf(n0, a.y, fmaf(n1, b.y, fmaf(n2, cc.y, fmaf(n3, dd.y, acc.y))));
        acc.z = fmaf(n0, a.z, fmaf(n1, b.z, fmaf(n2, cc.z, fmaf(n3, dd.z, acc.z))));
        acc.w = fmaf(n0, a.w, fmaf(n1, b.w, fmaf(n2, cc.w, fmaf(n3, dd.w, acc.w))));
    }
    for (; e < eend; e++) {
        int s0 = g_perm[e];
        float n0 = g_norm[s0];
        float4 a = F[s0 * 16 + c];
        acc.x = fmaf(n0, a.x, acc.x);
        acc.y = fmaf(n0, a.y, acc.y);
        acc.z = fmaf(n0, a.z, acc.z);
        acc.w = fmaf(n0, a.w, acc.w);
    }
    float nm = g_norm[n];
    ((float4*)g_S1n)[n * 16 + c] =
        make_float4(acc.x * nm, acc.y * nm, acc.z * nm, acc.w * nm);
}

// ---------------- gather pass 2: S2n = norm * A*(norm*S1n) ----------------
__global__ __launch_bounds__(256) void gather2_kernel() {
    int t = blockIdx.x * 256 + threadIdx.x;
    int n = t >> 4, c = t & 15;
    int e = g_row[n];
    int eend = g_row[n + 1];
    float4 acc = make_float4(0.f, 0.f, 0.f, 0.f);
    const float4* F = (const float4*)g_S1n;
    for (; e + 3 < eend; e += 4) {
        int s0 = g_perm[e], s1 = g_perm[e + 1];
        int s2 = g_perm[e + 2], s3 = g_perm[e + 3];
        float n0 = g_norm[s0], n1 = g_norm[s1];
        float n2 = g_norm[s2], n3 = g_norm[s3];
        float4 a = F[s0 * 16 + c];
        float4 b = F[s1 * 16 + c];
        float4 cc = F[s2 * 16 + c];
        float4 dd = F[s3 * 16 + c];
        acc.x = fmaf(n0, a.x, fmaf(n1, b.x, fmaf(n2, cc.x, fmaf(n3, dd.x, acc.x))));
        acc.y = fmaf(n0, a.y, fmaf(n1, b.y, fmaf(n2, cc.y, fmaf(n3, dd.y, acc.y))));
        acc.z = fmaf(n0, a.z, fmaf(n1, b.z, fmaf(n2, cc.z, fmaf(n3, dd.z, acc.z))));
        acc.w = fmaf(n0, a.w, fmaf(n1, b.w, fmaf(n2, cc.w, fmaf(n3, dd.w, acc.w))));
    }
    for (; e < eend; e++) {
        int s0 = g_perm[e];
        float n0 = g_norm[s0];
        float4 a = F[s0 * 16 + c];
        acc.x = fmaf(n0, a.x, acc.x);
        acc.y = fmaf(n0, a.y, acc.y);
        acc.z = fmaf(n0, a.z, acc.z);
        acc.w = fmaf(n0, a.w, acc.w);
    }
    float nm = g_norm[n];
    ((float4*)g_S2n)[n * 16 + c] =
        make_float4(acc.x * nm, acc.y * nm, acc.z * nm, acc.w * nm);
}

// ================= HMMA helpers =================
__device__ __forceinline__ void mma16816(float* c, const uint32_t* a,
                                         uint32_t b0, uint32_t b1) {
    asm volatile(
        "mma.sync.aligned.m16n8k16.row.col.f32.bf16.bf16.f32 "
        "{%0,%1,%2,%3}, {%4,%5,%6,%7}, {%8,%9}, {%0,%1,%2,%3};"
        : "+f"(c[0]), "+f"(c[1]), "+f"(c[2]), "+f"(c[3])
        : "r"(a[0]), "r"(a[1]), "r"(a[2]), "r"(a[3]), "r"(b0), "r"(b1));
}
__device__ __forceinline__ uint32_t pack2_bf16(float lo, float hi) {
    uint32_t r;
    asm("cvt.rn.bf16x2.f32 %0, %1, %2;" : "=r"(r) : "f"(hi), "f"(lo));
    return r;
}
#define ASTRIDE 33   // words per row (66 bf16)

// ---------------- GEMM (m selects A operand in device code) ----------------
__global__ __launch_bounds__(64) void gemm_tc_kernel(
    const float* __restrict__ feats,
    const float* __restrict__ W,
    float* __restrict__ out, int m) {
    __shared__ __align__(16) uint32_t sAhi[64 * ASTRIDE];
    __shared__ __align__(16) uint32_t sAlo[64 * ASTRIDE];
    __shared__ __align__(16) uint32_t sBhi[64 * ASTRIDE];
    __shared__ __align__(16) uint32_t sBlo[64 * ASTRIDE];

    int tid = threadIdx.x;
    int w = tid >> 5, lane = tid & 31;
    int g = lane >> 2, q = lane & 3;
    int rowbase = blockIdx.x * 64;

    const float* A = (m == 0) ? feats : (m == 1) ? g_S1n : g_S2n;

    {
        int grow = rowbase + tid;
        if (grow < N_NODES) {
            const float4* rp = (const float4*)(A + (size_t)grow * 64);
#pragma unroll
            for (int i = 0; i < 16; i++) {
                float4 v = rp[i];
                uint32_t bx = __float_as_uint(v.x) & 0xFFFF0000u;
                uint32_t by = __float_as_uint(v.y) & 0xFFFF0000u;
                uint32_t bz = __float_as_uint(v.z) & 0xFFFF0000u;
                uint32_t bw = __float_as_uint(v.w) & 0xFFFF0000u;
                sAhi[tid * ASTRIDE + 2 * i + 0] = __byte_perm(bx, by, 0x7632);
                sAhi[tid * ASTRIDE + 2 * i + 1] = __byte_perm(bz, bw, 0x7632);
                sAlo[tid * ASTRIDE + 2 * i + 0] =
                    pack2_bf16(v.x - __uint_as_float(bx), v.y - __uint_as_float(by));
                sAlo[tid * ASTRIDE + 2 * i + 1] =
                    pack2_bf16(v.z - __uint_as_float(bz), v.w - __uint_as_float(bw));
            }
        } else {
#pragma unroll
            for (int i = 0; i < 32; i++) {
                sAhi[tid * ASTRIDE + i] = 0;
                sAlo[tid * ASTRIDE + i] = 0;
            }
        }
    }
    {
        uint16_t* bh = (uint16_t*)sBhi;
        __nv_bfloat16* bl = (__nv_bfloat16*)sBlo;
#pragma unroll
        for (int i = 0; i < 64; i++) {
            int idx = tid + i * 64;
            float v = W[idx];
            int k = idx >> 6, n = idx & 63;
            uint32_t b = __float_as_uint(v) & 0xFFFF0000u;
            bh[n * 66 + k] = (uint16_t)(b >> 16);
            bl[n * 66 + k] = __float2bfloat16_rn(v - __uint_as_float(b));
        }
    }
    __syncthreads();

    float acc[2][8][4];
#pragma unroll
    for (int mt = 0; mt < 2; mt++)
#pragma unroll
        for (int nt = 0; nt < 8; nt++)
#pragma unroll
            for (int i = 0; i < 4; i++) acc[mt][nt][i] = 0.f;

#pragma unroll
    for (int ks = 0; ks < 4; ks++) {
        uint32_t bh[8][2], bl[8][2];
#pragma unroll
        for (int nt = 0; nt < 8; nt++) {
            int n = nt * 8 + g;
            int bw = n * ASTRIDE + q + ks * 8;
            bh[nt][0] = sBhi[bw];     bh[nt][1] = sBhi[bw + 4];
            bl[nt][0] = sBlo[bw];     bl[nt][1] = sBlo[bw + 4];
        }
#pragma unroll
        for (int mt = 0; mt < 2; mt++) {
            int r0 = w * 32 + mt * 16 + g;
            int aw0 = r0 * ASTRIDE + q + ks * 8;
            int aw1 = (r0 + 8) * ASTRIDE + q + ks * 8;
            uint32_t ahi[4] = {sAhi[aw0], sAhi[aw1], sAhi[aw0 + 4], sAhi[aw1 + 4]};
            uint32_t alo[4] = {sAlo[aw0], sAlo[aw1], sAlo[aw0 + 4], sAlo[aw1 + 4]};
#pragma unroll
            for (int nt = 0; nt < 8; nt++) {
                mma16816(acc[mt][nt], ahi, bh[nt][0], bh[nt][1]);
                mma16816(acc[mt][nt], ahi, bl[nt][0], bl[nt][1]);
                mma16816(acc[mt][nt], alo, bh[nt][0], bh[nt][1]);
            }
        }
    }

#pragma unroll
    for (int mt = 0; mt < 2; mt++) {
        int r0 = rowbase + w * 32 + mt * 16 + g;
#pragma unroll
        for (int nt = 0; nt < 8; nt++) {
            int col = m * 64 + nt * 8 + q * 2;
            if (r0 < N_NODES)
                *(float2*)(out + (size_t)r0 * 192 + col) =
                    make_float2(acc[mt][nt][0], acc[mt][nt][1]);
            if (r0 + 8 < N_NODES)
                *(float2*)(out + (size_t)(r0 + 8) * 192 + col) =
                    make_float2(acc[mt][nt][2], acc[mt][nt][3]);
        }
    }
}

// =================== launch ===================
extern "C" void kernel_launch(void* const* d_in, const int* in_sizes, int n_in,
                              void* d_out, int out_size) {
    const float* feats       = (const float*)d_in[0];
    const float* edge_weight = (const float*)d_in[1];
    const float* w0          = (const float*)d_in[2];
    const float* w1          = (const float*)d_in[3];
    const float* w2          = (const float*)d_in[4];
    const int*   src         = (const int*)d_in[5];
    const int*   dst         = (const int*)d_in[6];
    const int*   e_feat      = (const int*)d_in[7];
    float* out = (float*)d_out;

    static cudaStream_t s1 = nullptr, s2 = nullptr;
    static cudaEvent_t eStart, eG1, eM0, eM1;
    if (!s1) {
        cudaStreamCreateWithFlags(&s1, cudaStreamNonBlocking);
        cudaStreamCreateWithFlags(&s2, cudaStreamNonBlocking);
        cudaEventCreateWithFlags(&eStart, cudaEventDisableTiming);
        cudaEventCreateWithFlags(&eG1, cudaEventDisableTiming);
        cudaEventCreateWithFlags(&eM0, cudaEventDisableTiming);
        cudaEventCreateWithFlags(&eM1, cudaEventDisableTiming);
    }

    // fork at t=0: gemm m=0 depends only on feats
    cudaEventRecord(eStart, 0);
    cudaStreamWaitEvent(s2, eStart, 0);
    gemm_tc_kernel<<<GTILES, 64, 0, s2>>>(feats, w0, out, 0);
    cudaEventRecord(eM0, s2);

    // main pipeline
    hist_kernel<<<EBLKS, 256>>>(dst, e_feat, edge_weight);
    scan_fused_kernel<<<NBLK_SCAN, 256>>>();
    scatter_kernel<<<EBLKS, 256>>>(src, dst);
    gather1_kernel<<<(N_NODES * 16) / 256, 256>>>(feats);
    cudaEventRecord(eG1, 0);

    // s1: gemm m=1 overlaps gather2
    cudaStreamWaitEvent(s1, eG1, 0);
    gemm_tc_kernel<<<GTILES, 64, 0, s1>>>(feats, w1, out, 1);
    cudaEventRecord(eM1, s1);

    // main: gather2 + gemm m=2
    gather2_kernel<<<(N_NODES * 16) / 256, 256>>>();
    gemm_tc_kernel<<<GTILES, 64>>>(feats, w2, out, 2);

    // join
    cudaStreamWaitEvent(0, eM0, 0);
    cudaStreamWaitEvent(0, eM1, 0);
}